// round 16
// baseline (speedup 1.0000x reference)
#include <cuda_runtime.h>
#include <math.h>
#include <stdint.h>

#define B_ 4
#define C_ 64
#define H_ 128
#define W_ 128
#define HW_ (H_*W_)
#define O_ 64
#define OFFS (B_*H_*18*W_)   // per-chunk offset plane, transposed layout [b,h][18][w]

// Packed f32x2 helpers (Blackwell)
#define FMA2(acc, a, b) asm("fma.rn.f32x2 %0, %1, %2, %0;" : "+l"(acc) : "l"(a), "l"(b))
#define DUP2(dst, f)    asm("mov.b64 %0, {%1, %1};" : "=l"(dst) : "f"(f))
#define UNPK2(lo, hi, v) asm("mov.b64 {%0, %1}, %2;" : "=f"(lo), "=f"(hi) : "l"(v))

// Scratch
__device__ __align__(16) float g_xt[B_*HW_*C_];       // x in NHWC
__device__ __align__(16) float g_off[4*OFFS];         // partial offsets [chunk][b,h][18][w]
__device__ __align__(16) float g_wdt[9*C_*O_];        // w_def [k][c][o]
__device__ __align__(16) float g_partial[B_*H_*16*2]; // [b][h][group][2]

// ---------------- K0 (fused pre-kernel) ----------------
// 1-D grid, 256 threads/block, min 3 blocks/SM:
//   blocks [0, 512)      : offset conv, chunk of 16 input channels x 4 rows (2 rows/thread)
//   blocks [512, 4608)   : transpose, one 32x32 tile per block
//   blocks [4608, 4624)  : w_def reorder
__global__ void __launch_bounds__(256, 3) k_pre(const float* __restrict__ x,
                                                const float* __restrict__ w_off,
                                                const float* __restrict__ b_off,
                                                const float* __restrict__ w_def) {
    __shared__ __align__(16) float smu[2880];   // 11,520 B (union of roles)
    int bx = blockIdx.x;
    int tid = threadIdx.x;

    if (bx >= 4608) {
        // ---- w_def [o][c][3][3] -> g_wdt [k][c][o] ----
        int flat = bx - 4608;
        for (int i = flat*256 + tid; i < 9*64*64; i += 16*256) {
            int o = i & 63;
            int c = (i >> 6) & 63;
            int k = i >> 12;
            g_wdt[i] = w_def[(o*64 + c)*9 + k];
        }
        return;
    }

    if (bx >= 512) {
        // ---- transpose one 32x32 tile ----
        float (*tile)[33] = (float(*)[33])smu;
        int t = bx - 512;
        int p0 = (t & 511) * 32;
        int c0 = ((t >> 9) & 1) * 32;
        int b  = t >> 10;
        int tx = tid & 31, ty0 = tid >> 5;
#pragma unroll
        for (int i = 0; i < 4; i++) {
            int ty = ty0 + i*8;
            tile[ty][tx] = x[(b*C_ + c0 + ty)*HW_ + p0 + tx];
        }
        __syncthreads();
#pragma unroll
        for (int i = 0; i < 4; i++) {
            int ty = ty0 + i*8;
            g_xt[(b*HW_ + p0 + ty)*C_ + c0 + tx] = tile[tx][ty];
        }
        return;
    }

    // ---- offset conv chunk: 16 input channels, 4 rows per block, 2 rows per thread ----
    int q  = bx >> 7;            // channel chunk 0..3
    int t  = bx & 127;
    int b  = t >> 5;
    int hq = t & 31;
    int c0 = q * 16;
    int h0 = hq * 4;

    float* ws = smu;             // [16*9][20]  (pad cols 18,19 feed discarded acc[9])
    for (int i = tid; i < 16*9*18; i += 256) {
        int o = i % 18;
        int cj = i / 18;
        int c = cj / 9, j = cj % 9;
        ws[cj*20 + o] = w_off[(o*64 + c0 + c)*9 + j];
    }
    __syncthreads();

    int rp = tid >> 7;           // row-pair index 0/1
    int h  = h0 + rp*2;          // this thread covers rows h and h+1
    int w  = tid & 127;
    unsigned long long acc0[10], acc1[10];
#pragma unroll
    for (int qq = 0; qq < 10; qq++) { acc0[qq] = 0ull; acc1[qq] = 0ull; }

    const float* xb = x + (size_t)b * C_ * HW_ + (size_t)c0 * HW_;
    bool wl = (w > 0), wr = (w < W_-1);

    for (int c = 0; c < 16; c++) {
        const float* xc = xb + c*HW_;
        float xr[4][3];          // rows h-1 .. h+2
#pragma unroll
        for (int r = 0; r < 4; r++) {
            int y = h - 1 + r;
            bool yv = (y >= 0 && y < H_);
            const float* row = xc + y*W_;
            xr[r][0] = (yv && wl) ? row[w-1] : 0.f;
            xr[r][1] =  yv        ? row[w]   : 0.f;
            xr[r][2] = (yv && wr) ? row[w+1] : 0.f;
        }
#pragma unroll
        for (int j = 0; j < 9; j++) {
            int jy = j / 3, jx = j % 3;
            unsigned long long v0, v1;
            DUP2(v0, xr[jy][jx]);
            DUP2(v1, xr[jy+1][jx]);
            const ulonglong2* wp = (const ulonglong2*)&ws[(c*9 + j)*20];
#pragma unroll
            for (int qq = 0; qq < 5; qq++) {
                ulonglong2 wv = wp[qq];
                FMA2(acc0[2*qq+0], wv.x, v0);
                FMA2(acc0[2*qq+1], wv.y, v0);
                FMA2(acc1[2*qq+0], wv.x, v1);
                FMA2(acc1[2*qq+1], wv.y, v1);
            }
        }
    }

    // transposed store: [b,h][o][w], coalesced over w; two rows
    float* op0 = &g_off[(size_t)q*OFFS + (size_t)(b*H_ + h)*18*128 + w];
    float* op1 = op0 + 18*128;
    if (q == 0) {
#pragma unroll
        for (int qq = 0; qq < 9; qq++) {
            float lo, hi;
            UNPK2(lo, hi, acc0[qq]);
            op0[(2*qq+0)*128] = lo + b_off[2*qq+0];
            op0[(2*qq+1)*128] = hi + b_off[2*qq+1];
            UNPK2(lo, hi, acc1[qq]);
            op1[(2*qq+0)*128] = lo + b_off[2*qq+0];
            op1[(2*qq+1)*128] = hi + b_off[2*qq+1];
        }
    } else {
#pragma unroll
        for (int qq = 0; qq < 9; qq++) {
            float lo, hi;
            UNPK2(lo, hi, acc0[qq]);
            op0[(2*qq+0)*128] = lo;
            op0[(2*qq+1)*128] = hi;
            UNPK2(lo, hi, acc1[qq]);
            op1[(2*qq+0)*128] = lo;
            op1[(2*qq+1)*128] = hi;
        }
    }
}

// ---------------- K2: pipelined deformable sample + GEMM ----------------
// Block = 1 row (128 px), 128 threads, 5 blocks/SM.
// 36 units (tap x 16-channel quarter). Phase p: gather(unit p) + GEMM(unit p-1).
// smem (floats):
#define SBUF0  0        // 16c x 128px = 2048
#define SBUF1  2048
#define SWD0   4096     // 16c x 64o = 1024
#define SWD1   5120
#define SADDR  6144     // 4 x 128 int
#define SBW    6656     // 4 x 128 float
#define SMF    7168     // 28,672 bytes

__global__ void __launch_bounds__(128, 5) k_main(const float* __restrict__ b_def,
                                                 float* __restrict__ out) {
    extern __shared__ float sm[];
    int h = blockIdx.x;
    int b = blockIdx.y;
    int tid = threadIdx.x;
    int warp = tid >> 5, col = tid & 31;
    int o0 = warp * 16;
    int g32 = tid >> 2, l4 = tid & 3;   // gather: pixel-in-pass, channel-group

    const float* offh = g_off + (size_t)(b*H_ + h)*18*128;   // transposed rows
    const float* xb = g_xt + (size_t)b * HW_ * C_;
    int*   s_addr = (int*)(sm + SADDR);
    float* s_bw   = sm + SBW;

    unsigned long long acc[8][4];   // [o-pair][px]
#pragma unroll
    for (int i = 0; i < 8; i++)
#pragma unroll
        for (int j = 0; j < 4; j++) acc[i][j] = 0ull;

#pragma unroll 1
    for (int p = 0; p < 37; p++) {
        bool do_g = (p < 36), do_m = (p >= 1);
        int kg = p >> 2, qc = p & 3;

        // tap boundaries: compute this tap's corner addresses + bilinear weights
        if (qc == 0 && do_g) {
            int w_a = tid;
            int ry = (2*kg)*128 + tid, rx = (2*kg+1)*128 + tid;
            float dy = offh[ry] + offh[OFFS + ry] + offh[2*OFFS + ry] + offh[3*OFFS + ry];
            float dx = offh[rx] + offh[OFFS + rx] + offh[2*OFFS + rx] + offh[3*OFFS + rx];
            float py  = (float)(h + kg/3 - 1) + dy;
            float pxf = (float)(w_a + kg%3 - 1) + dx;
            float y0f = floorf(py), x0f = floorf(pxf);
            float wy = py - y0f, wx = pxf - x0f;
            int y0 = (int)y0f, x0 = (int)x0f;
            int y1 = y0 + 1, x1 = x0 + 1;
            float vy0 = (y0 >= 0 && y0 < H_) ? 1.f : 0.f;
            float vy1 = (y1 >= 0 && y1 < H_) ? 1.f : 0.f;
            float vx0 = (x0 >= 0 && x0 < W_) ? 1.f : 0.f;
            float vx1 = (x1 >= 0 && x1 < W_) ? 1.f : 0.f;
            int y0c = min(max(y0,0),H_-1), y1c = min(max(y1,0),H_-1);
            int x0c = min(max(x0,0),W_-1), x1c = min(max(x1,0),W_-1);
            s_addr[0*128+tid] = (y0c*W_ + x0c)*C_;  s_bw[0*128+tid] = (1.f-wy)*(1.f-wx)*vy0*vx0;
            s_addr[1*128+tid] = (y0c*W_ + x1c)*C_;  s_bw[1*128+tid] = (1.f-wy)*wx*vy0*vx1;
            s_addr[2*128+tid] = (y1c*W_ + x0c)*C_;  s_bw[2*128+tid] = wy*(1.f-wx)*vy1*vx0;
            s_addr[3*128+tid] = (y1c*W_ + x1c)*C_;  s_bw[3*128+tid] = wy*wx*vy1*vx1;
            __syncthreads();
        }

        float*       sbw  = sm + ((p&1)     ? SBUF1 : SBUF0);
        const float* sbr  = sm + (((p-1)&1) ? SBUF1 : SBUF0);
        const float* swdr = sm + (((p-1)&1) ? SWD1  : SWD0);
        int chb = qc*16 + l4*4;

        // copy weights for unit p into swd[p&1] (read next phase): 16c x 64o = 256 float4
        if (do_g) {
            const float4* src = (const float4*)(g_wdt + (size_t)(kg*64 + qc*16)*64);
            float4* dst = (float4*)(sm + ((p&1) ? SWD1 : SWD0));
            dst[tid]       = src[tid];
            dst[tid + 128] = src[tid + 128];
        }

#pragma unroll
        for (int pass = 0; pass < 4; pass++) {
            int pxi = pass*32 + g32;
            float4 v0, v1, v2, v3;
            float bw0, bw1, bw2, bw3;
            if (do_g) {
                int a0 = s_addr[pxi], a1 = s_addr[128+pxi], a2 = s_addr[256+pxi], a3 = s_addr[384+pxi];
                bw0 = s_bw[pxi]; bw1 = s_bw[128+pxi]; bw2 = s_bw[256+pxi]; bw3 = s_bw[384+pxi];
                v0 = *(const float4*)(xb + a0 + chb);
                v1 = *(const float4*)(xb + a1 + chb);
                v2 = *(const float4*)(xb + a2 + chb);
                v3 = *(const float4*)(xb + a3 + chb);
            }
            if (do_m) {
#pragma unroll
                for (int j = 0; j < 4; j++) {
                    int cc = pass*4 + j;                 // local channel 0..15
                    float4 s4 = *(const float4*)&sbr[cc*128 + ((col ^ ((cc>>2)<<1)) << 2)];
                    unsigned long long d0, d1, d2, d3;
                    DUP2(d0, s4.x); DUP2(d1, s4.y); DUP2(d2, s4.z); DUP2(d3, s4.w);
                    const ulonglong2* wp = (const ulonglong2*)&swdr[cc*64 + o0];
                    ulonglong2 wA = wp[0], wB = wp[1], wC = wp[2], wD = wp[3];
                    FMA2(acc[0][0], wA.x, d0); FMA2(acc[0][1], wA.x, d1);
                    FMA2(acc[0][2], wA.x, d2); FMA2(acc[0][3], wA.x, d3);
                    FMA2(acc[1][0], wA.y, d0); FMA2(acc[1][1], wA.y, d1);
                    FMA2(acc[1][2], wA.y, d2); FMA2(acc[1][3], wA.y, d3);
                    FMA2(acc[2][0], wB.x, d0); FMA2(acc[2][1], wB.x, d1);
                    FMA2(acc[2][2], wB.x, d2); FMA2(acc[2][3], wB.x, d3);
                    FMA2(acc[3][0], wB.y, d0); FMA2(acc[3][1], wB.y, d1);
                    FMA2(acc[3][2], wB.y, d2); FMA2(acc[3][3], wB.y, d3);
                    FMA2(acc[4][0], wC.x, d0); FMA2(acc[4][1], wC.x, d1);
                    FMA2(acc[4][2], wC.x, d2); FMA2(acc[4][3], wC.x, d3);
                    FMA2(acc[5][0], wC.y, d0); FMA2(acc[5][1], wC.y, d1);
                    FMA2(acc[5][2], wC.y, d2); FMA2(acc[5][3], wC.y, d3);
                    FMA2(acc[6][0], wD.x, d0); FMA2(acc[6][1], wD.x, d1);
                    FMA2(acc[6][2], wD.x, d2); FMA2(acc[6][3], wD.x, d3);
                    FMA2(acc[7][0], wD.y, d0); FMA2(acc[7][1], wD.y, d1);
                    FMA2(acc[7][2], wD.y, d2); FMA2(acc[7][3], wD.y, d3);
                }
            }
            if (do_g) {
                float sx = bw0*v0.x + bw1*v1.x + bw2*v2.x + bw3*v3.x;
                float sy = bw0*v0.y + bw1*v1.y + bw2*v2.y + bw3*v3.y;
                float sz = bw0*v0.z + bw1*v1.z + bw2*v2.z + bw3*v3.z;
                float sw = bw0*v0.w + bw1*v1.w + bw2*v2.w + bw3*v3.w;
                int scg = ((pxi>>2) ^ (l4<<1)) & 31;
                float* d = &sbw[(l4*4)*128 + (scg<<2) + (pxi & 3)];
                d[0]   = sx;
                d[128] = sy;
                d[256] = sz;
                d[384] = sw;
            }
        }
        __syncthreads();
    }

    // ---- epilogue: bias, store pre-GN, per-group partials ----
    float sg[4] = {0,0,0,0}, qg[4] = {0,0,0,0};
    float* outb = out + (size_t)b * O_ * HW_ + h*W_ + col*4;
#pragma unroll
    for (int j = 0; j < 8; j++) {
        int oe = o0 + 2*j, oo = oe + 1;
        float be = b_def[oe], bo = b_def[oo];
        float4 ve, vo;
        UNPK2(ve.x, vo.x, acc[j][0]);
        UNPK2(ve.y, vo.y, acc[j][1]);
        UNPK2(ve.z, vo.z, acc[j][2]);
        UNPK2(ve.w, vo.w, acc[j][3]);
        ve.x += be; ve.y += be; ve.z += be; ve.w += be;
        vo.x += bo; vo.y += bo; vo.z += bo; vo.w += bo;
        *(float4*)(outb + (size_t)oe * HW_) = ve;
        *(float4*)(outb + (size_t)oo * HW_) = vo;
        int gi = j >> 1;
        sg[gi] += ve.x + ve.y + ve.z + ve.w + vo.x + vo.y + vo.z + vo.w;
        qg[gi] += ve.x*ve.x + ve.y*ve.y + ve.z*ve.z + ve.w*ve.w
                + vo.x*vo.x + vo.y*vo.y + vo.z*vo.z + vo.w*vo.w;
    }
#pragma unroll
    for (int off = 16; off > 0; off >>= 1) {
#pragma unroll
        for (int gi = 0; gi < 4; gi++) {
            sg[gi] += __shfl_xor_sync(0xffffffffu, sg[gi], off);
            qg[gi] += __shfl_xor_sync(0xffffffffu, qg[gi], off);
        }
    }
    if (col == 0) {
        float* pp = &g_partial[(size_t)((b*H_ + h)*16)*2];
#pragma unroll
        for (int gi = 0; gi < 4; gi++) {
            int grp = warp*4 + gi;
            pp[grp*2 + 0] = sg[gi];
            pp[grp*2 + 1] = qg[gi];
        }
    }
}

// ---------------- K3: GN stats (fused, per-block) + affine + LeakyReLU ----------------
// Block = 1024 consecutive floats of out (all within one (b, c)).
__global__ void __launch_bounds__(256) k_norm(float* __restrict__ out,
                                              const float* __restrict__ gn_w,
                                              const float* __restrict__ gn_b) {
    __shared__ float red[8];
    int blk = blockIdx.x;
    int tid = threadIdx.x;
    int c = (blk >> 4) & 63;
    int b = blk >> 10;
    int g = c >> 2;

    // recompute group stats from per-row partials (fixed-order, deterministic)
    float s = 0.f, q = 0.f;
    if (tid < 128) {
        const float* pp = &g_partial[(size_t)(((b*H_ + tid)*16) + g)*2];
        s = pp[0];
        q = pp[1];
    }
#pragma unroll
    for (int off = 16; off > 0; off >>= 1) {
        s += __shfl_xor_sync(0xffffffffu, s, off);
        q += __shfl_xor_sync(0xffffffffu, q, off);
    }
    if (tid < 128 && (tid & 31) == 0) {
        red[(tid >> 5)*2 + 0] = s;
        red[(tid >> 5)*2 + 1] = q;
    }
    __syncthreads();
    s = red[0] + red[2] + red[4] + red[6];
    q = red[1] + red[3] + red[5] + red[7];
    const float N = 4.f * (float)HW_;
    float mu  = s / N;
    float inv = rsqrtf(q / N - mu*mu + 1e-5f);

    float sc = gn_w[c] * inv;
    float sh = gn_b[c] - mu * sc;
    int i = blk * 256 + tid;    // float4 index
    float4 v = ((float4*)out)[i];
    v.x = v.x*sc + sh; v.x = (v.x >= 0.f) ? v.x : 0.2f*v.x;
    v.y = v.y*sc + sh; v.y = (v.y >= 0.f) ? v.y : 0.2f*v.y;
    v.z = v.z*sc + sh; v.z = (v.z >= 0.f) ? v.z : 0.2f*v.z;
    v.w = v.w*sc + sh; v.w = (v.w >= 0.f) ? v.w : 0.2f*v.w;
    ((float4*)out)[i] = v;
}

extern "C" void kernel_launch(void* const* d_in, const int* in_sizes, int n_in,
                              void* d_out, int out_size) {
    const float* x     = (const float*)d_in[0];
    const float* w_off = (const float*)d_in[1];
    const float* b_off = (const float*)d_in[2];
    const float* w_def = (const float*)d_in[3];
    const float* b_def = (const float*)d_in[4];
    const float* gn_w  = (const float*)d_in[5];
    const float* gn_b  = (const float*)d_in[6];
    float* out = (float*)d_out;

    cudaFuncSetAttribute(k_main, cudaFuncAttributeMaxDynamicSharedMemorySize,
                         SMF * (int)sizeof(float));

    k_pre<<<4624, 256>>>(x, w_off, b_off, w_def);
    k_main<<<dim3(H_, B_), 128, SMF * sizeof(float)>>>(b_def, out);
    k_norm<<<4096, 256>>>(out, gn_w, gn_b);
}

// round 17
// speedup vs baseline: 1.5559x; 1.5559x over previous
#include <cuda_runtime.h>
#include <math.h>
#include <stdint.h>

#define B_ 4
#define C_ 64
#define H_ 128
#define W_ 128
#define HW_ (H_*W_)
#define O_ 64
#define OFFS (B_*H_*18*W_)   // per-chunk offset plane, transposed layout [b,h][18][w]

// Packed f32x2 helpers (Blackwell)
#define FMA2(acc, a, b) asm("fma.rn.f32x2 %0, %1, %2, %0;" : "+l"(acc) : "l"(a), "l"(b))
#define DUP2(dst, f)    asm("mov.b64 %0, {%1, %1};" : "=l"(dst) : "f"(f))
#define UNPK2(lo, hi, v) asm("mov.b64 {%0, %1}, %2;" : "=f"(lo), "=f"(hi) : "l"(v))

// Scratch
__device__ __align__(16) float g_xt[B_*HW_*C_];       // x in NHWC
__device__ __align__(16) float g_off[4*OFFS];         // partial offsets [chunk][b,h][18][w]
__device__ __align__(16) float g_wdt[9*C_*O_];        // w_def [k][c][o]
__device__ __align__(16) float g_partial[B_*H_*16*2]; // [b][h][group][2]

// ---------------- K0 (fused pre-kernel) ----------------
// 1-D grid, 256 threads/block, min 3 blocks/SM:
//   blocks [0, 512)      : offset conv, chunk of 16 input channels x 4 rows (2 rows/thread)
//   blocks [512, 4608)   : transpose, one 32x32 tile per block
//   blocks [4608, 4624)  : w_def reorder
__global__ void __launch_bounds__(256, 3) k_pre(const float* __restrict__ x,
                                                const float* __restrict__ w_off,
                                                const float* __restrict__ b_off,
                                                const float* __restrict__ w_def) {
    __shared__ __align__(16) float smu[2880];   // 11,520 B (union of roles)
    int bx = blockIdx.x;
    int tid = threadIdx.x;

    if (bx >= 4608) {
        // ---- w_def [o][c][3][3] -> g_wdt [k][c][o] ----
        int flat = bx - 4608;
        for (int i = flat*256 + tid; i < 9*64*64; i += 16*256) {
            int o = i & 63;
            int c = (i >> 6) & 63;
            int k = i >> 12;
            g_wdt[i] = w_def[(o*64 + c)*9 + k];
        }
        return;
    }

    if (bx >= 512) {
        // ---- transpose one 32x32 tile ----
        float (*tile)[33] = (float(*)[33])smu;
        int t = bx - 512;
        int p0 = (t & 511) * 32;
        int c0 = ((t >> 9) & 1) * 32;
        int b  = t >> 10;
        int tx = tid & 31, ty0 = tid >> 5;
#pragma unroll
        for (int i = 0; i < 4; i++) {
            int ty = ty0 + i*8;
            tile[ty][tx] = x[(b*C_ + c0 + ty)*HW_ + p0 + tx];
        }
        __syncthreads();
#pragma unroll
        for (int i = 0; i < 4; i++) {
            int ty = ty0 + i*8;
            g_xt[(b*HW_ + p0 + ty)*C_ + c0 + tx] = tile[tx][ty];
        }
        return;
    }

    // ---- offset conv chunk: 16 input channels, 4 rows per block, 2 rows per thread ----
    int q  = bx >> 7;            // channel chunk 0..3
    int t  = bx & 127;
    int b  = t >> 5;
    int hq = t & 31;
    int c0 = q * 16;
    int h0 = hq * 4;

    float* ws = smu;             // [16*9][20]  (pad cols 18,19 feed discarded acc[9])
    for (int i = tid; i < 16*9*18; i += 256) {
        int o = i % 18;
        int cj = i / 18;
        int c = cj / 9, j = cj % 9;
        ws[cj*20 + o] = w_off[(o*64 + c0 + c)*9 + j];
    }
    __syncthreads();

    int rp = tid >> 7;           // row-pair index 0/1
    int h  = h0 + rp*2;          // this thread covers rows h and h+1
    int w  = tid & 127;
    unsigned long long acc0[10], acc1[10];
#pragma unroll
    for (int qq = 0; qq < 10; qq++) { acc0[qq] = 0ull; acc1[qq] = 0ull; }

    const float* xb = x + (size_t)b * C_ * HW_ + (size_t)c0 * HW_;
    bool wl = (w > 0), wr = (w < W_-1);

    for (int c = 0; c < 16; c++) {
        const float* xc = xb + c*HW_;
        float xr[4][3];          // rows h-1 .. h+2
#pragma unroll
        for (int r = 0; r < 4; r++) {
            int y = h - 1 + r;
            bool yv = (y >= 0 && y < H_);
            const float* row = xc + y*W_;
            xr[r][0] = (yv && wl) ? row[w-1] : 0.f;
            xr[r][1] =  yv        ? row[w]   : 0.f;
            xr[r][2] = (yv && wr) ? row[w+1] : 0.f;
        }
#pragma unroll
        for (int j = 0; j < 9; j++) {
            int jy = j / 3, jx = j % 3;
            unsigned long long v0, v1;
            DUP2(v0, xr[jy][jx]);
            DUP2(v1, xr[jy+1][jx]);
            const ulonglong2* wp = (const ulonglong2*)&ws[(c*9 + j)*20];
#pragma unroll
            for (int qq = 0; qq < 5; qq++) {
                ulonglong2 wv = wp[qq];
                FMA2(acc0[2*qq+0], wv.x, v0);
                FMA2(acc0[2*qq+1], wv.y, v0);
                FMA2(acc1[2*qq+0], wv.x, v1);
                FMA2(acc1[2*qq+1], wv.y, v1);
            }
        }
    }

    // transposed store: [b,h][o][w], coalesced over w; two rows
    float* op0 = &g_off[(size_t)q*OFFS + (size_t)(b*H_ + h)*18*128 + w];
    float* op1 = op0 + 18*128;
    if (q == 0) {
#pragma unroll
        for (int qq = 0; qq < 9; qq++) {
            float lo, hi;
            UNPK2(lo, hi, acc0[qq]);
            op0[(2*qq+0)*128] = lo + b_off[2*qq+0];
            op0[(2*qq+1)*128] = hi + b_off[2*qq+1];
            UNPK2(lo, hi, acc1[qq]);
            op1[(2*qq+0)*128] = lo + b_off[2*qq+0];
            op1[(2*qq+1)*128] = hi + b_off[2*qq+1];
        }
    } else {
#pragma unroll
        for (int qq = 0; qq < 9; qq++) {
            float lo, hi;
            UNPK2(lo, hi, acc0[qq]);
            op0[(2*qq+0)*128] = lo;
            op0[(2*qq+1)*128] = hi;
            UNPK2(lo, hi, acc1[qq]);
            op1[(2*qq+0)*128] = lo;
            op1[(2*qq+1)*128] = hi;
        }
    }
}

// ---------------- K2: pipelined deformable sample + GEMM ----------------
// Block = 1 row (128 px), 128 threads, 4 blocks/SM.  [exact R13/R15 code — smem ≤ 53,248 B]
#define SBUF0  0        // 32c x 128px
#define SBUF1  4096
#define SWD0   8192     // 32c x 64o
#define SWD1   10240
#define SADDR  12288    // 4 x 128 int
#define SBW    12800    // 4 x 128 float
#define SMF    13312    // 53248 bytes

__global__ void __launch_bounds__(128, 4) k_main(const float* __restrict__ b_def,
                                                 float* __restrict__ out) {
    extern __shared__ float sm[];
    int h = blockIdx.x;
    int b = blockIdx.y;
    int tid = threadIdx.x;
    int warp = tid >> 5, col = tid & 31;
    int o0 = warp * 16;
    int g8 = tid >> 3, l8 = tid & 7;   // gather: pixel-in-pass, channel-group

    const float* offh = g_off + (size_t)(b*H_ + h)*18*128;   // transposed rows
    const float* xb = g_xt + (size_t)b * HW_ * C_;
    int*   s_addr = (int*)(sm + SADDR);
    float* s_bw   = sm + SBW;

    unsigned long long acc[8][4];   // [o-pair][px]
#pragma unroll
    for (int i = 0; i < 8; i++)
#pragma unroll
        for (int j = 0; j < 4; j++) acc[i][j] = 0ull;

#pragma unroll 1
    for (int p = 0; p < 19; p++) {
        bool do_g = (p < 18), do_m = (p >= 1);
        int kg = p >> 1, hg = p & 1;

        // even phases: compute this tap's corner addresses + bilinear weights
        if (hg == 0 && do_g) {
            int w_a = tid;
            int ry = (2*kg)*128 + tid, rx = (2*kg+1)*128 + tid;
            float dy = offh[ry] + offh[OFFS + ry] + offh[2*OFFS + ry] + offh[3*OFFS + ry];
            float dx = offh[rx] + offh[OFFS + rx] + offh[2*OFFS + rx] + offh[3*OFFS + rx];
            float py  = (float)(h + kg/3 - 1) + dy;
            float pxf = (float)(w_a + kg%3 - 1) + dx;
            float y0f = floorf(py), x0f = floorf(pxf);
            float wy = py - y0f, wx = pxf - x0f;
            int y0 = (int)y0f, x0 = (int)x0f;
            int y1 = y0 + 1, x1 = x0 + 1;
            float vy0 = (y0 >= 0 && y0 < H_) ? 1.f : 0.f;
            float vy1 = (y1 >= 0 && y1 < H_) ? 1.f : 0.f;
            float vx0 = (x0 >= 0 && x0 < W_) ? 1.f : 0.f;
            float vx1 = (x1 >= 0 && x1 < W_) ? 1.f : 0.f;
            int y0c = min(max(y0,0),H_-1), y1c = min(max(y1,0),H_-1);
            int x0c = min(max(x0,0),W_-1), x1c = min(max(x1,0),W_-1);
            s_addr[0*128+tid] = (y0c*W_ + x0c)*C_;  s_bw[0*128+tid] = (1.f-wy)*(1.f-wx)*vy0*vx0;
            s_addr[1*128+tid] = (y0c*W_ + x1c)*C_;  s_bw[1*128+tid] = (1.f-wy)*wx*vy0*vx1;
            s_addr[2*128+tid] = (y1c*W_ + x0c)*C_;  s_bw[2*128+tid] = wy*(1.f-wx)*vy1*vx0;
            s_addr[3*128+tid] = (y1c*W_ + x1c)*C_;  s_bw[3*128+tid] = wy*wx*vy1*vx1;
            __syncthreads();
        }

        float*       sbw  = sm + ((p&1)     ? SBUF1 : SBUF0);
        const float* sbr  = sm + (((p-1)&1) ? SBUF1 : SBUF0);
        const float* swdr = sm + (((p-1)&1) ? SWD1  : SWD0);
        int chb = hg*32 + l8*4;

        // copy weights for unit p into swd[p&1] (read next phase)
        if (do_g) {
            const float4* src = (const float4*)(g_wdt + (size_t)(kg*64 + hg*32)*64);
            float4* dst = (float4*)(sm + ((p&1) ? SWD1 : SWD0));
#pragma unroll
            for (int i = 0; i < 4; i++) dst[tid + i*128] = src[tid + i*128];
        }

#pragma unroll
        for (int pass = 0; pass < 8; pass++) {
            int pxi = pass*16 + g8;
            float4 v0, v1, v2, v3;
            float bw0, bw1, bw2, bw3;
            if (do_g) {
                int a0 = s_addr[pxi], a1 = s_addr[128+pxi], a2 = s_addr[256+pxi], a3 = s_addr[384+pxi];
                bw0 = s_bw[pxi]; bw1 = s_bw[128+pxi]; bw2 = s_bw[256+pxi]; bw3 = s_bw[384+pxi];
                v0 = *(const float4*)(xb + a0 + chb);
                v1 = *(const float4*)(xb + a1 + chb);
                v2 = *(const float4*)(xb + a2 + chb);
                v3 = *(const float4*)(xb + a3 + chb);
            }
            if (do_m) {
#pragma unroll
                for (int j = 0; j < 4; j++) {
                    int cc = pass*4 + j;                 // local channel 0..31
                    float4 s4 = *(const float4*)&sbr[cc*128 + ((col ^ (cc>>2)) << 2)];
                    unsigned long long d0, d1, d2, d3;
                    DUP2(d0, s4.x); DUP2(d1, s4.y); DUP2(d2, s4.z); DUP2(d3, s4.w);
                    const ulonglong2* wp = (const ulonglong2*)&swdr[cc*64 + o0];
                    ulonglong2 wA = wp[0], wB = wp[1], wC = wp[2], wD = wp[3];
                    FMA2(acc[0][0], wA.x, d0); FMA2(acc[0][1], wA.x, d1);
                    FMA2(acc[0][2], wA.x, d2); FMA2(acc[0][3], wA.x, d3);
                    FMA2(acc[1][0], wA.y, d0); FMA2(acc[1][1], wA.y, d1);
                    FMA2(acc[1][2], wA.y, d2); FMA2(acc[1][3], wA.y, d3);
                    FMA2(acc[2][0], wB.x, d0); FMA2(acc[2][1], wB.x, d1);
                    FMA2(acc[2][2], wB.x, d2); FMA2(acc[2][3], wB.x, d3);
                    FMA2(acc[3][0], wB.y, d0); FMA2(acc[3][1], wB.y, d1);
                    FMA2(acc[3][2], wB.y, d2); FMA2(acc[3][3], wB.y, d3);
                    FMA2(acc[4][0], wC.x, d0); FMA2(acc[4][1], wC.x, d1);
                    FMA2(acc[4][2], wC.x, d2); FMA2(acc[4][3], wC.x, d3);
                    FMA2(acc[5][0], wC.y, d0); FMA2(acc[5][1], wC.y, d1);
                    FMA2(acc[5][2], wC.y, d2); FMA2(acc[5][3], wC.y, d3);
                    FMA2(acc[6][0], wD.x, d0); FMA2(acc[6][1], wD.x, d1);
                    FMA2(acc[6][2], wD.x, d2); FMA2(acc[6][3], wD.x, d3);
                    FMA2(acc[7][0], wD.y, d0); FMA2(acc[7][1], wD.y, d1);
                    FMA2(acc[7][2], wD.y, d2); FMA2(acc[7][3], wD.y, d3);
                }
            }
            if (do_g) {
                float sx = bw0*v0.x + bw1*v1.x + bw2*v2.x + bw3*v3.x;
                float sy = bw0*v0.y + bw1*v1.y + bw2*v2.y + bw3*v3.y;
                float sz = bw0*v0.z + bw1*v1.z + bw2*v2.z + bw3*v3.z;
                float sw = bw0*v0.w + bw1*v1.w + bw2*v2.w + bw3*v3.w;
                int scg = (((pxi>>2) ^ l8) << 2) + (pxi & 3);
                float* d = &sbw[(l8*4)*128 + scg];
                d[0]   = sx;
                d[128] = sy;
                d[256] = sz;
                d[384] = sw;
            }
        }
        __syncthreads();
    }

    // ---- epilogue: bias, store pre-GN, per-group partials ----
    float sg[4] = {0,0,0,0}, qg[4] = {0,0,0,0};
    float* outb = out + (size_t)b * O_ * HW_ + h*W_ + col*4;
#pragma unroll
    for (int j = 0; j < 8; j++) {
        int oe = o0 + 2*j, oo = oe + 1;
        float be = b_def[oe], bo = b_def[oo];
        float4 ve, vo;
        UNPK2(ve.x, vo.x, acc[j][0]);
        UNPK2(ve.y, vo.y, acc[j][1]);
        UNPK2(ve.z, vo.z, acc[j][2]);
        UNPK2(ve.w, vo.w, acc[j][3]);
        ve.x += be; ve.y += be; ve.z += be; ve.w += be;
        vo.x += bo; vo.y += bo; vo.z += bo; vo.w += bo;
        *(float4*)(outb + (size_t)oe * HW_) = ve;
        *(float4*)(outb + (size_t)oo * HW_) = vo;
        int gi = j >> 1;
        sg[gi] += ve.x + ve.y + ve.z + ve.w + vo.x + vo.y + vo.z + vo.w;
        qg[gi] += ve.x*ve.x + ve.y*ve.y + ve.z*ve.z + ve.w*ve.w
                + vo.x*vo.x + vo.y*vo.y + vo.z*vo.z + vo.w*vo.w;
    }
#pragma unroll
    for (int off = 16; off > 0; off >>= 1) {
#pragma unroll
        for (int gi = 0; gi < 4; gi++) {
            sg[gi] += __shfl_xor_sync(0xffffffffu, sg[gi], off);
            qg[gi] += __shfl_xor_sync(0xffffffffu, qg[gi], off);
        }
    }
    if (col == 0) {
        float* pp = &g_partial[(size_t)((b*H_ + h)*16)*2];
#pragma unroll
        for (int gi = 0; gi < 4; gi++) {
            int grp = warp*4 + gi;
            pp[grp*2 + 0] = sg[gi];
            pp[grp*2 + 1] = qg[gi];
        }
    }
}

// ---------------- K3: GN stats (fused, per-block) + affine + LeakyReLU ----------------
// Coarsened 4x: block = 4096 consecutive floats (one quarter of one (b, c) plane).
__global__ void __launch_bounds__(256) k_norm(float* __restrict__ out,
                                              const float* __restrict__ gn_w,
                                              const float* __restrict__ gn_b) {
    __shared__ float red[8];
    int blk = blockIdx.x;
    int tid = threadIdx.x;
    int quarter = blk & 3;
    int c = (blk >> 2) & 63;
    int b = blk >> 8;
    int g = c >> 2;

    // recompute group stats from per-row partials (fixed-order, deterministic)
    float s = 0.f, q = 0.f;
    if (tid < 128) {
        const float* pp = &g_partial[(size_t)(((b*H_ + tid)*16) + g)*2];
        s = pp[0];
        q = pp[1];
    }
#pragma unroll
    for (int off = 16; off > 0; off >>= 1) {
        s += __shfl_xor_sync(0xffffffffu, s, off);
        q += __shfl_xor_sync(0xffffffffu, q, off);
    }
    if (tid < 128 && (tid & 31) == 0) {
        red[(tid >> 5)*2 + 0] = s;
        red[(tid >> 5)*2 + 1] = q;
    }
    __syncthreads();
    s = red[0] + red[2] + red[4] + red[6];
    q = red[1] + red[3] + red[5] + red[7];
    const float N = 4.f * (float)HW_;
    float mu  = s / N;
    float inv = rsqrtf(q / N - mu*mu + 1e-5f);

    float sc = gn_w[c] * inv;
    float sh = gn_b[c] - mu * sc;
    int base = ((b*64 + c)*4096) + quarter*1024;   // float4 index
#pragma unroll
    for (int j = 0; j < 4; j++) {
        int i = base + j*256 + tid;
        float4 v = ((float4*)out)[i];
        v.x = v.x*sc + sh; v.x = (v.x >= 0.f) ? v.x : 0.2f*v.x;
        v.y = v.y*sc + sh; v.y = (v.y >= 0.f) ? v.y : 0.2f*v.y;
        v.z = v.z*sc + sh; v.z = (v.z >= 0.f) ? v.z : 0.2f*v.z;
        v.w = v.w*sc + sh; v.w = (v.w >= 0.f) ? v.w : 0.2f*v.w;
        ((float4*)out)[i] = v;
    }
}

extern "C" void kernel_launch(void* const* d_in, const int* in_sizes, int n_in,
                              void* d_out, int out_size) {
    const float* x     = (const float*)d_in[0];
    const float* w_off = (const float*)d_in[1];
    const float* b_off = (const float*)d_in[2];
    const float* w_def = (const float*)d_in[3];
    const float* b_def = (const float*)d_in[4];
    const float* gn_w  = (const float*)d_in[5];
    const float* gn_b  = (const float*)d_in[6];
    float* out = (float*)d_out;

    cudaFuncSetAttribute(k_main, cudaFuncAttributeMaxDynamicSharedMemorySize,
                         SMF * (int)sizeof(float));

    k_pre<<<4624, 256>>>(x, w_off, b_off, w_def);
    k_main<<<dim3(H_, B_), 128, SMF * sizeof(float)>>>(b_def, out);
    k_norm<<<1024, 256>>>(out, gn_w, gn_b);
}